// round 15
// baseline (speedup 1.0000x reference)
#include <cuda_runtime.h>
#include <cuda_bf16.h>
#include <cuda_fp16.h>
#include <cstdint>

#define N_NODES 50000
#define N_EDGES 1600000
#define IN_F    256
#define HID_F   128
#define OUT_F   40
#define SCAN_B  256
#define N_BLKS  ((N_NODES + SCAN_B - 1) / SCAN_B)   // 196
#define CONVW_ELEMS (IN_F * HID_F + HID_F * HID_F)  // 49152
#define CONVW_BLKS  (CONVW_ELEMS / 256)             // 192
#define CHUNK_A 25088                                // 196*128, first-half rows

// ---------------- scratch (device globals; no allocs allowed) ----------------
__device__ int   g_is64;
__device__ int   g_degc[N_NODES];
__device__ float g_dinv[N_NODES];
__device__ int   g_off[N_NODES + 1];
__device__ int   g_cursor[N_NODES];
__device__ int   g_bsum[N_BLKS];
__device__ int   g_csrc[N_EDGES];
__device__ __align__(16) __half g_w1h [HID_F * IN_F];     // W1^T [n][k] fp16
__device__ __align__(16) __half g_w2h [HID_F * HID_F];    // W2^T [n][k] fp16
__device__ __align__(16) __half g_hwh [N_NODES * HID_F];  // fp16 h (layer1: unscaled; layer2: dinv-scaled)
__device__ __align__(16) __half g_aggh[N_NODES * HID_F];  // fp16 relu'd agg
__device__ __align__(16) __half g_hw40[N_NODES * OUT_F];  // fp16 dinv-scaled layer-3 h

// ------------- fused init: zero degc + detect dtype + convert weights --------
__global__ __launch_bounds__(256) void init_convw_kernel(
    const int* __restrict__ ei32,
    const float* __restrict__ W1, const float* __restrict__ W2)
{
    int b = blockIdx.x, t = threadIdx.x;
    if (b < N_BLKS) {
        int i = b * SCAN_B + t;
        if (i < N_NODES) g_degc[i] = 0;
        if (i == 0) {
            int ok = 1;
            #pragma unroll 1
            for (int k = 0; k < 512; k++) {
                if (ei32[2 * k + 1] != 0) { ok = 0; break; }
            }
            g_is64 = ok;
        }
    } else {
        int i = (b - N_BLKS) * 256 + t;
        if (i < IN_F * HID_F) {                  // W1: [256][128]
            int k = i / HID_F, n = i % HID_F;
            g_w1h[n * IN_F + k] = __float2half_rn(W1[i]);
        } else if (i < CONVW_ELEMS) {
            int j = i - IN_F * HID_F;            // W2: [128][128]
            int k = j / HID_F, n = j % HID_F;
            g_w2h[n * HID_F + k] = __float2half_rn(W2[j]);
        }
    }
}

__device__ __forceinline__ int load_id(const void* ei, int idx) {
    if (g_is64) return (int)((const long long*)ei)[idx];
    return ((const int*)ei)[idx];
}

__global__ void deg_kernel(const void* __restrict__ ei) {
    int e = blockIdx.x * blockDim.x + threadIdx.x;
    if (e < N_EDGES) {
        int d = load_id(ei, N_EDGES + e);
        if ((unsigned)d < (unsigned)N_NODES) atomicAdd(&g_degc[d], 1);
    }
}

// ---------------- scan phase 1: per-block local excl scan + dinv ----------------
__global__ __launch_bounds__(SCAN_B) void scan_p1_kernel() {
    __shared__ int s_ws[8];
    int t = threadIdx.x, lane = t & 31, w = t >> 5;
    int i = blockIdx.x * SCAN_B + t;
    int v = (i < N_NODES) ? g_degc[i] : 0;
    if (i < N_NODES) g_dinv[i] = rsqrtf((float)v + 1.0f);   // +1 self-loop
    int x = v;
    #pragma unroll
    for (int o = 1; o < 32; o <<= 1) {
        int y = __shfl_up_sync(0xFFFFFFFFu, x, o);
        if (lane >= o) x += y;
    }
    if (lane == 31) s_ws[w] = x;
    __syncthreads();
    if (w == 0 && lane < 8) {
        int s = s_ws[lane];
        #pragma unroll
        for (int o = 1; o < 8; o <<= 1) {
            int y = __shfl_up_sync(0xFFu, s, o);
            if (lane >= o) s += y;
        }
        s_ws[lane] = s;
    }
    __syncthreads();
    int base = (w == 0) ? 0 : s_ws[w - 1];
    int excl = x - v + base;
    if (i < N_NODES) g_off[i] = excl;
    if (t == SCAN_B - 1) g_bsum[blockIdx.x] = x + base;      // block total
}

// ---------------- scan phase 2+3 merged: every block scans bsum locally -------
__global__ __launch_bounds__(256) void scan_p23_kernel() {
    __shared__ int s_ws[8];
    __shared__ int s_incl[256];
    int t = threadIdx.x, lane = t & 31, w = t >> 5;
    int v = (t < N_BLKS) ? g_bsum[t] : 0;
    int x = v;
    #pragma unroll
    for (int o = 1; o < 32; o <<= 1) {
        int y = __shfl_up_sync(0xFFFFFFFFu, x, o);
        if (lane >= o) x += y;
    }
    if (lane == 31) s_ws[w] = x;
    __syncthreads();
    if (w == 0 && lane < 8) {
        int s = s_ws[lane];
        #pragma unroll
        for (int o = 1; o < 8; o <<= 1) {
            int y = __shfl_up_sync(0xFFu, s, o);
            if (lane >= o) s += y;
        }
        s_ws[lane] = s;
    }
    __syncthreads();
    int wbase = (w == 0) ? 0 : s_ws[w - 1];
    s_incl[t] = x + wbase;          // inclusive scan of bsum
    __syncthreads();

    int base  = (blockIdx.x == 0) ? 0 : s_incl[blockIdx.x - 1];
    int i = blockIdx.x * SCAN_B + t;
    if (i < N_NODES) {
        int o = g_off[i] + base;
        g_off[i] = o;
        g_cursor[i] = o;
    }
    if (blockIdx.x == 0 && t == 0) g_off[N_NODES] = s_incl[N_BLKS - 1];
}

// fill: only src ids
__global__ void fill_kernel(const void* __restrict__ ei) {
    int e = blockIdx.x * blockDim.x + threadIdx.x;
    if (e < N_EDGES) {
        int s = load_id(ei, e);
        int d = load_id(ei, N_EDGES + e);
        if ((unsigned)s < (unsigned)N_NODES && (unsigned)d < (unsigned)N_NODES) {
            int pos = atomicAdd(&g_cursor[d], 1);
            g_csrc[pos] = s;
        }
    }
}

// ---------------- FP16 MMA helpers ----------------
__device__ __forceinline__ void mma_f16(
    float* d, const uint32_t* a, const uint32_t* b)
{
    asm volatile(
        "mma.sync.aligned.m16n8k16.row.col.f32.f16.f16.f32 "
        "{%0,%1,%2,%3}, {%4,%5,%6,%7}, {%8,%9}, {%0,%1,%2,%3};"
        : "+f"(d[0]), "+f"(d[1]), "+f"(d[2]), "+f"(d[3])
        : "r"(a[0]), "r"(a[1]), "r"(a[2]), "r"(a[3]), "r"(b[0]), "r"(b[1]));
}

__device__ __forceinline__ uint32_t pack_h2(float a, float b) {
    __half2 h = __floats2half2_rn(a, b);
    return *(uint32_t*)&h;
}

// ---------------- FP16 GEMM: rows [row_base, row_base+rows) of g_hwh ----------
// A: fp32 external (a16=0) or fp16 g_aggh (a16=1). Bw: [128][K] fp16 n-major.
__global__ __launch_bounds__(256, 2) void hgemm128_kernel(
    const float* __restrict__ A32, int a16, int b_sel, int scaleEpi,
    int row_base, int M, int K)
{
    const __half* A16 = g_aggh;
    const __half* Bw  = b_sel ? g_w2h : g_w1h;
    __half* C = g_hwh;

    __shared__ __align__(16) uint32_t As[128 * 20];
    __shared__ __align__(16) uint32_t Bs[128 * 20];

    int tid  = threadIdx.x;
    int lane = tid & 31;
    int warp = tid >> 5;
    int r = lane >> 2, c = lane & 3;
    int m_base = (warp >> 2) * 64;
    int n_base = (warp & 3) * 32;
    int block_row = row_base + blockIdx.x * 128;

    float acc[4][4][4];
    #pragma unroll
    for (int i = 0; i < 4; i++)
        #pragma unroll
        for (int j = 0; j < 4; j++)
            #pragma unroll
            for (int q = 0; q < 4; q++) acc[i][j][q] = 0.f;

    int a_m[4], a_kq[4];
    #pragma unroll
    for (int j = 0; j < 4; j++) {
        int u = tid + 256 * j;
        a_m[j]  = u >> 3;
        a_kq[j] = u & 7;
    }
    int c_row0 = tid >> 2;
    int c_row1 = (tid + 256) >> 2;
    int cq = tid & 3;
    int a_r0 = min(block_row + c_row0, M - 1);
    int a_r1 = min(block_row + c_row1, M - 1);

    float4 pa[4];
    uint4  pa16[2];
    uint4  pb16[2];

    if (a16) {
        pa16[0] = *(const uint4*)(A16 + (size_t)a_r0 * K + cq * 8);
        pa16[1] = *(const uint4*)(A16 + (size_t)a_r1 * K + cq * 8);
    } else {
        #pragma unroll
        for (int j = 0; j < 4; j++) {
            int gm = block_row + a_m[j];
            pa[j] = (gm < M) ? *(const float4*)&A32[(size_t)gm * K + a_kq[j] * 4]
                             : make_float4(0.f, 0.f, 0.f, 0.f);
        }
    }
    pb16[0] = *(const uint4*)(Bw + (size_t)c_row0 * K + cq * 8);
    pb16[1] = *(const uint4*)(Bw + (size_t)c_row1 * K + cq * 8);

    for (int k0 = 0; k0 < K; k0 += 32) {
        __syncthreads();
        if (a16) {
            *(uint4*)&As[c_row0 * 20 + cq * 4] = pa16[0];
            *(uint4*)&As[c_row1 * 20 + cq * 4] = pa16[1];
        } else {
            #pragma unroll
            for (int j = 0; j < 4; j++) {
                int base = a_m[j] * 20 + a_kq[j] * 2;
                As[base + 0] = pack_h2(pa[j].x, pa[j].y);
                As[base + 1] = pack_h2(pa[j].z, pa[j].w);
            }
        }
        *(uint4*)&Bs[c_row0 * 20 + cq * 4] = pb16[0];
        *(uint4*)&Bs[c_row1 * 20 + cq * 4] = pb16[1];
        __syncthreads();

        if (k0 + 32 < K) {
            int kn = k0 + 32;
            if (a16) {
                pa16[0] = *(const uint4*)(A16 + (size_t)a_r0 * K + kn + cq * 8);
                pa16[1] = *(const uint4*)(A16 + (size_t)a_r1 * K + kn + cq * 8);
            } else {
                #pragma unroll
                for (int j = 0; j < 4; j++) {
                    int gm = block_row + a_m[j];
                    pa[j] = (gm < M) ? *(const float4*)&A32[(size_t)gm * K + kn + a_kq[j] * 4]
                                     : make_float4(0.f, 0.f, 0.f, 0.f);
                }
            }
            pb16[0] = *(const uint4*)(Bw + (size_t)c_row0 * K + kn + cq * 8);
            pb16[1] = *(const uint4*)(Bw + (size_t)c_row1 * K + kn + cq * 8);
        }

        #pragma unroll
        for (int kk = 0; kk < 2; kk++) {
            int p0 = kk * 8 + c;
            uint32_t bf[4][2];
            #pragma unroll
            for (int ni = 0; ni < 4; ni++) {
                int n = n_base + ni * 8 + r;
                bf[ni][0] = Bs[n * 20 + p0];
                bf[ni][1] = Bs[n * 20 + p0 + 4];
            }
            #pragma unroll
            for (int mi = 0; mi < 4; mi++) {
                int i0 = (m_base + mi * 16 + r) * 20 + p0;
                int i1 = (m_base + mi * 16 + 8 + r) * 20 + p0;
                uint32_t af[4];
                af[0] = As[i0];     af[1] = As[i1];
                af[2] = As[i0 + 4]; af[3] = As[i1 + 4];
                #pragma unroll
                for (int ni = 0; ni < 4; ni++)
                    mma_f16(acc[mi][ni], af, bf[ni]);
            }
        }
    }

    #pragma unroll
    for (int mi = 0; mi < 4; mi++) {
        int gr0 = block_row + m_base + mi * 16 + r;
        float d0 = 1.f, d1 = 1.f;
        if (scaleEpi) {
            d0 = (gr0 < M)     ? g_dinv[gr0]     : 0.f;
            d1 = (gr0 + 8 < M) ? g_dinv[gr0 + 8] : 0.f;
        }
        #pragma unroll
        for (int ni = 0; ni < 4; ni++) {
            int col = n_base + ni * 8 + 2 * c;
            if (gr0 < M)
                *(__half2*)&C[(size_t)gr0 * 128 + col] =
                    __floats2half2_rn(acc[mi][ni][0] * d0, acc[mi][ni][1] * d0);
            if (gr0 + 8 < M)
                *(__half2*)&C[(size_t)(gr0 + 8) * 128 + col] =
                    __floats2half2_rn(acc[mi][ni][2] * d1, acc[mi][ni][3] * d1);
        }
    }
}

// ---------------- layer-3 SGEMM: rows [row_base, ...) ----------------
__global__ __launch_bounds__(256) void sgemm40_kernel(
    const float* __restrict__ B, int row_base, int M)
{
    const __half* A = g_aggh;
    __half* C = g_hw40;
    __shared__ float As[16][128];
    __shared__ float Bs[16][40];

    int tid = threadIdx.x;
    int block_row = row_base + blockIdx.x * 128;
    int tr = tid >> 3;
    int tc = tid & 7;

    float acc[4][5] = {};

    for (int k0 = 0; k0 < HID_F; k0 += 16) {
        #pragma unroll
        for (int p = 0; p < 2; p++) {
            int i = tid + p * 256;
            int m = i >> 2;
            int kq = (i & 3) << 2;
            int gm = block_row + m;
            float2 f01 = make_float2(0.f, 0.f), f23 = make_float2(0.f, 0.f);
            if (gm < M) {
                uint2 u = *(const uint2*)&A[(size_t)gm * HID_F + k0 + kq];
                f01 = __half22float2(*(__half2*)&u.x);
                f23 = __half22float2(*(__half2*)&u.y);
            }
            As[kq + 0][m] = f01.x;
            As[kq + 1][m] = f01.y;
            As[kq + 2][m] = f23.x;
            As[kq + 3][m] = f23.y;
        }
        if (tid < 160) {
            int k = tid / 10;
            int n4 = (tid % 10) * 4;
            *(float4*)&Bs[k][n4] = *(const float4*)&B[(size_t)(k0 + k) * OUT_F + n4];
        }
        __syncthreads();

        #pragma unroll
        for (int k = 0; k < 16; k++) {
            float4 a4 = *(const float4*)&As[k][tr * 4];
            float a[4] = {a4.x, a4.y, a4.z, a4.w};
            float b[5];
            #pragma unroll
            for (int j = 0; j < 5; j++) b[j] = Bs[k][tc * 5 + j];
            #pragma unroll
            for (int i = 0; i < 4; i++)
                #pragma unroll
                for (int j = 0; j < 5; j++)
                    acc[i][j] += a[i] * b[j];
        }
        __syncthreads();
    }

    #pragma unroll
    for (int i = 0; i < 4; i++) {
        int gm = block_row + tr * 4 + i;
        if (gm >= M) continue;
        float di = g_dinv[gm];
        #pragma unroll
        for (int j = 0; j < 5; j++)
            C[(size_t)gm * OUT_F + tc * 5 + j] = __float2half_rn(acc[i][j] * di);
    }
}

// ---- aggregation 128-wide over node range [nbase, nbase+ncount) --------------
template <int L1>
__global__ __launch_bounds__(256) void aggregate16_kernel(
    const float* __restrict__ bias, int nbase, int ncount)
{
    int wi = (blockIdx.x * blockDim.x + threadIdx.x) >> 5;
    int lane = threadIdx.x & 31;
    if (wi >= ncount) return;
    int warp = nbase + wi;
    const uint2* HW = (const uint2*)g_hwh;
    int beg = g_off[warp], end = g_off[warp + 1];
    float4 acc = make_float4(0.f, 0.f, 0.f, 0.f);

    #define ACC_EDGE(sv) do {                                       \
        uint2 u_ = HW[(size_t)(sv) * 32 + lane];                    \
        float2 f01_ = __half22float2(*(__half2*)&u_.x);             \
        float2 f23_ = __half22float2(*(__half2*)&u_.y);             \
        if (L1) {                                                   \
            float ds_ = g_dinv[sv];                                 \
            acc.x += ds_ * f01_.x; acc.y += ds_ * f01_.y;           \
            acc.z += ds_ * f23_.x; acc.w += ds_ * f23_.y;           \
        } else {                                                    \
            acc.x += f01_.x; acc.y += f01_.y;                       \
            acc.z += f23_.x; acc.w += f23_.y;                       \
        }                                                           \
    } while (0)

    int j = beg;
    for (; j + 4 <= end; j += 4) {
        int s0 = g_csrc[j],     s1 = g_csrc[j + 1];
        int s2 = g_csrc[j + 2], s3 = g_csrc[j + 3];
        ACC_EDGE(s0); ACC_EDGE(s1); ACC_EDGE(s2); ACC_EDGE(s3);
    }
    for (; j < end; j++) { int sv = g_csrc[j]; ACC_EDGE(sv); }
    #undef ACC_EDGE

    float di = g_dinv[warp];
    uint2 u = HW[(size_t)warp * 32 + lane];
    float2 f01 = __half22float2(*(__half2*)&u.x);
    float2 f23 = __half22float2(*(__half2*)&u.y);
    float selfs = L1 ? di : 1.f;
    float4 b4 = ((const float4*)bias)[lane];
    float rx = fmaxf((acc.x + selfs * f01.x) * di + b4.x, 0.f);
    float ry = fmaxf((acc.y + selfs * f01.y) * di + b4.y, 0.f);
    float rz = fmaxf((acc.z + selfs * f23.x) * di + b4.z, 0.f);
    float rw = fmaxf((acc.w + selfs * f23.y) * di + b4.w, 0.f);
    __half2 h0 = __floats2half2_rn(rx, ry);
    __half2 h1 = __floats2half2_rn(rz, rw);
    ((uint2*)g_aggh)[(size_t)warp * 32 + lane] =
        make_uint2(*(uint32_t*)&h0, *(uint32_t*)&h1);
}

// ---- aggregation (40-wide) + fused log_softmax -> d_out ----------------------
__global__ __launch_bounds__(256) void aggregate40_lsm_kernel(
    const float* __restrict__ bias, float* __restrict__ out)
{
    int warp = (blockIdx.x * blockDim.x + threadIdx.x) >> 5;
    int lane = threadIdx.x & 31;
    if (warp >= N_NODES) return;
    bool active = lane < 10;
    const uint2* HW = (const uint2*)g_hw40;
    int beg = g_off[warp], end = g_off[warp + 1];
    float4 acc = make_float4(0.f, 0.f, 0.f, 0.f);

    #define ACC_E40(sv) do {                                        \
        if (active) {                                               \
            uint2 u_ = HW[(size_t)(sv) * 10 + lane];                \
            float2 f01_ = __half22float2(*(__half2*)&u_.x);         \
            float2 f23_ = __half22float2(*(__half2*)&u_.y);         \
            acc.x += f01_.x; acc.y += f01_.y;                       \
            acc.z += f23_.x; acc.w += f23_.y;                       \
        }                                                           \
    } while (0)

    int j = beg;
    for (; j + 4 <= end; j += 4) {
        int s0 = g_csrc[j],     s1 = g_csrc[j + 1];
        int s2 = g_csrc[j + 2], s3 = g_csrc[j + 3];
        ACC_E40(s0); ACC_E40(s1); ACC_E40(s2); ACC_E40(s3);
    }
    for (; j < end; j++) { int sv = g_csrc[j]; ACC_E40(sv); }
    #undef ACC_E40

    float4 v = make_float4(-3.4e38f, -3.4e38f, -3.4e38f, -3.4e38f);
    if (active) {
        float di = g_dinv[warp];
        uint2 u = HW[(size_t)warp * 10 + lane];
        float2 f01 = __half22float2(*(__half2*)&u.x);
        float2 f23 = __half22float2(*(__half2*)&u.y);
        float4 b4 = ((const float4*)bias)[lane];
        v.x = (acc.x + f01.x) * di + b4.x;
        v.y = (acc.y + f01.y) * di + b4.y;
        v.z = (acc.z + f23.x) * di + b4.z;
        v.w = (acc.w + f23.y) * di + b4.w;
    }

    float m = fmaxf(fmaxf(v.x, v.y), fmaxf(v.z, v.w));
    #pragma unroll
    for (int o = 16; o > 0; o >>= 1) m = fmaxf(m, __shfl_xor_sync(0xFFFFFFFFu, m, o));
    float s = 0.f;
    if (active)
        s = __expf(v.x - m) + __expf(v.y - m) + __expf(v.z - m) + __expf(v.w - m);
    #pragma unroll
    for (int o = 16; o > 0; o >>= 1) s += __shfl_xor_sync(0xFFFFFFFFu, s, o);
    float lse = m + __logf(s);

    if (active) {
        float4 r = make_float4(v.x - lse, v.y - lse, v.z - lse, v.w - lse);
        ((float4*)out)[(size_t)warp * 10 + lane] = r;
    }
}

// ---------------- launch ----------------
extern "C" void kernel_launch(void* const* d_in, const int* in_sizes, int n_in,
                              void* d_out, int out_size)
{
    const float* x  = (const float*)d_in[0];
    const void*  ei = d_in[1];
    const float* W1 = (const float*)d_in[2];
    const float* b1 = (const float*)d_in[3];
    const float* W2 = (const float*)d_in[4];
    const float* b2 = (const float*)d_in[5];
    const float* W3 = (const float*)d_in[6];
    const float* b3 = (const float*)d_in[7];
    float* out = (float*)d_out;

    const int TB = 256;
    const int NB = N_NODES - CHUNK_A;               // second-half node count
    int aggA_grid = (CHUNK_A * 32 + TB - 1) / TB;
    int aggB_grid = (NB * 32 + TB - 1) / TB;
    int agg_grid  = (N_NODES * 32 + TB - 1) / TB;
    int gA_grid = CHUNK_A / 128;                    // 196
    int gB_grid = (NB + 127) / 128;                 // 195
    int gemm_grid = (N_NODES + 127) / 128;
    int edge_grid = (N_EDGES + TB - 1) / TB;

    // One-time resources (first call = uncaptured correctness run).
    struct Res {
        cudaStream_t s2;
        cudaEvent_t evFork, evG1, evA1, evA1B, evG2, evA2, evA2B, evS40;
        Res() {
            cudaStreamCreateWithFlags(&s2, cudaStreamNonBlocking);
            cudaEvent_t* evs[8] = {&evFork, &evG1, &evA1, &evA1B, &evG2,
                                   &evA2, &evA2B, &evS40};
            for (int i = 0; i < 8; i++)
                cudaEventCreateWithFlags(evs[i], cudaEventDisableTiming);
        }
    };
    static Res R;

    // ---- phase 0: CSR chain (main) ∥ layer-1 GEMM (s2) ----
    init_convw_kernel<<<N_BLKS + CONVW_BLKS, TB>>>((const int*)ei, W1, W2); // 1
    cudaEventRecord(R.evFork, 0);
    deg_kernel<<<edge_grid, TB>>>(ei);                                       // 2
    scan_p1_kernel<<<N_BLKS, SCAN_B>>>();                                    // 3
    cudaStreamWaitEvent(R.s2, R.evFork, 0);
    hgemm128_kernel<<<gemm_grid, 256, 0, R.s2>>>(x, 0, 0, 0, 0, N_NODES, IN_F); // 4 (profiled)
    cudaEventRecord(R.evG1, R.s2);
    scan_p23_kernel<<<N_BLKS, 256>>>();                                      // 5
    fill_kernel<<<edge_grid, TB>>>(ei);                                      // 6
    cudaStreamWaitEvent(0, R.evG1, 0);

    // ---- phase 1: agg1 (split) with hgemm2_A overlapped on s2 ----
    aggregate16_kernel<1><<<aggA_grid, TB>>>(b1, 0, CHUNK_A);                // 7
    cudaEventRecord(R.evA1, 0);
    aggregate16_kernel<1><<<aggB_grid, TB>>>(b1, CHUNK_A, NB);               // 8
    cudaEventRecord(R.evA1B, 0);
    cudaStreamWaitEvent(R.s2, R.evA1, 0);
    hgemm128_kernel<<<gA_grid, 256, 0, R.s2>>>(nullptr, 1, 1, 1, 0, N_NODES, HID_F);       // 9
    cudaStreamWaitEvent(R.s2, R.evA1B, 0);
    hgemm128_kernel<<<gB_grid, 256, 0, R.s2>>>(nullptr, 1, 1, 1, CHUNK_A, N_NODES, HID_F); // 10
    cudaEventRecord(R.evG2, R.s2);
    cudaStreamWaitEvent(0, R.evG2, 0);

    // ---- phase 2: agg2 (split) with sgemm40_A overlapped on s2 ----
    aggregate16_kernel<0><<<aggA_grid, TB>>>(b2, 0, CHUNK_A);                // 11
    cudaEventRecord(R.evA2, 0);
    aggregate16_kernel<0><<<aggB_grid, TB>>>(b2, CHUNK_A, NB);               // 12
    cudaEventRecord(R.evA2B, 0);
    cudaStreamWaitEvent(R.s2, R.evA2, 0);
    sgemm40_kernel<<<gA_grid, 256, 0, R.s2>>>(W3, 0, N_NODES);               // 13
    cudaStreamWaitEvent(R.s2, R.evA2B, 0);
    sgemm40_kernel<<<gB_grid, 256, 0, R.s2>>>(W3, CHUNK_A, N_NODES);         // 14
    cudaEventRecord(R.evS40, R.s2);
    cudaStreamWaitEvent(0, R.evS40, 0);

    // ---- phase 3: final aggregate + log_softmax ----
    aggregate40_lsm_kernel<<<agg_grid, TB>>>(b3, out);                       // 15
}

// round 16
// speedup vs baseline: 1.1787x; 1.1787x over previous
#include <cuda_runtime.h>
#include <cuda_bf16.h>
#include <cuda_fp16.h>
#include <cstdint>

#define N_NODES 50000
#define N_EDGES 1600000
#define IN_F    256
#define HID_F   128
#define OUT_F   40
#define SCAN_B  256
#define N_BLKS  ((N_NODES + SCAN_B - 1) / SCAN_B)   // 196
#define CONVW_ELEMS (IN_F * HID_F + HID_F * HID_F)  // 49152
#define CONVW_BLKS  (CONVW_ELEMS / 256)             // 192

// ---------------- scratch (device globals; no allocs allowed) ----------------
__device__ int   g_is64;
__device__ int   g_degc[N_NODES];
__device__ float g_dinv[N_NODES];
__device__ int   g_off[N_NODES + 1];
__device__ int   g_cursor[N_NODES];
__device__ int   g_bsum[N_BLKS];
__device__ int   g_csrc[N_EDGES];
__device__ __align__(16) __half g_w1h [HID_F * IN_F];     // W1^T [n][k] fp16
__device__ __align__(16) __half g_w2h [HID_F * HID_F];    // W2^T [n][k] fp16
__device__ __align__(16) __half g_hwh [N_NODES * HID_F];  // fp16 h (layer1: unscaled; layer2: dinv-scaled)
__device__ __align__(16) __half g_aggh[N_NODES * HID_F];  // fp16 relu'd agg
__device__ __align__(16) __half g_hw40[N_NODES * OUT_F];  // fp16 dinv-scaled layer-3 h

// ------------- fused init: zero degc + detect dtype + convert weights --------
__global__ __launch_bounds__(256) void init_convw_kernel(
    const int* __restrict__ ei32,
    const float* __restrict__ W1, const float* __restrict__ W2)
{
    int b = blockIdx.x, t = threadIdx.x;
    if (b < N_BLKS) {
        int i = b * SCAN_B + t;
        if (i < N_NODES) g_degc[i] = 0;
        if (i == 0) {
            int ok = 1;
            #pragma unroll 1
            for (int k = 0; k < 512; k++) {
                if (ei32[2 * k + 1] != 0) { ok = 0; break; }
            }
            g_is64 = ok;
        }
    } else {
        int i = (b - N_BLKS) * 256 + t;
        if (i < IN_F * HID_F) {                  // W1: [256][128]
            int k = i / HID_F, n = i % HID_F;
            g_w1h[n * IN_F + k] = __float2half_rn(W1[i]);
        } else if (i < CONVW_ELEMS) {
            int j = i - IN_F * HID_F;            // W2: [128][128]
            int k = j / HID_F, n = j % HID_F;
            g_w2h[n * HID_F + k] = __float2half_rn(W2[j]);
        }
    }
}

// ---------------- deg: 2 edges per thread, vectorized id loads ----------------
__global__ void deg_kernel(const void* __restrict__ ei) {
    int e2 = blockIdx.x * blockDim.x + threadIdx.x;     // edge-pair index
    if (2 * e2 >= N_EDGES) return;
    int d0, d1;
    if (g_is64) {
        longlong2 v = ((const longlong2*)ei)[N_EDGES / 2 + e2];
        d0 = (int)v.x; d1 = (int)v.y;
    } else {
        int2 v = ((const int2*)((const int*)ei + N_EDGES))[e2];
        d0 = v.x; d1 = v.y;
    }
    if ((unsigned)d0 < (unsigned)N_NODES) atomicAdd(&g_degc[d0], 1);
    if ((unsigned)d1 < (unsigned)N_NODES) atomicAdd(&g_degc[d1], 1);
}

// ---------------- scan phase 1: per-block local excl scan + dinv ----------------
__global__ __launch_bounds__(SCAN_B) void scan_p1_kernel() {
    __shared__ int s_ws[8];
    int t = threadIdx.x, lane = t & 31, w = t >> 5;
    int i = blockIdx.x * SCAN_B + t;
    int v = (i < N_NODES) ? g_degc[i] : 0;
    if (i < N_NODES) g_dinv[i] = rsqrtf((float)v + 1.0f);   // +1 self-loop
    int x = v;
    #pragma unroll
    for (int o = 1; o < 32; o <<= 1) {
        int y = __shfl_up_sync(0xFFFFFFFFu, x, o);
        if (lane >= o) x += y;
    }
    if (lane == 31) s_ws[w] = x;
    __syncthreads();
    if (w == 0 && lane < 8) {
        int s = s_ws[lane];
        #pragma unroll
        for (int o = 1; o < 8; o <<= 1) {
            int y = __shfl_up_sync(0xFFu, s, o);
            if (lane >= o) s += y;
        }
        s_ws[lane] = s;
    }
    __syncthreads();
    int base = (w == 0) ? 0 : s_ws[w - 1];
    int excl = x - v + base;
    if (i < N_NODES) g_off[i] = excl;
    if (t == SCAN_B - 1) g_bsum[blockIdx.x] = x + base;      // block total
}

// ---------------- scan phase 2+3 merged: every block scans bsum locally -------
__global__ __launch_bounds__(256) void scan_p23_kernel() {
    __shared__ int s_ws[8];
    __shared__ int s_incl[256];
    int t = threadIdx.x, lane = t & 31, w = t >> 5;
    int v = (t < N_BLKS) ? g_bsum[t] : 0;
    int x = v;
    #pragma unroll
    for (int o = 1; o < 32; o <<= 1) {
        int y = __shfl_up_sync(0xFFFFFFFFu, x, o);
        if (lane >= o) x += y;
    }
    if (lane == 31) s_ws[w] = x;
    __syncthreads();
    if (w == 0 && lane < 8) {
        int s = s_ws[lane];
        #pragma unroll
        for (int o = 1; o < 8; o <<= 1) {
            int y = __shfl_up_sync(0xFFu, s, o);
            if (lane >= o) s += y;
        }
        s_ws[lane] = s;
    }
    __syncthreads();
    int wbase = (w == 0) ? 0 : s_ws[w - 1];
    s_incl[t] = x + wbase;          // inclusive scan of bsum
    __syncthreads();

    int base  = (blockIdx.x == 0) ? 0 : s_incl[blockIdx.x - 1];
    int i = blockIdx.x * SCAN_B + t;
    if (i < N_NODES) {
        int o = g_off[i] + base;
        g_off[i] = o;
        g_cursor[i] = o;
    }
    if (blockIdx.x == 0 && t == 0) g_off[N_NODES] = s_incl[N_BLKS - 1];
}

// ---------------- fill: 2 edges per thread, vectorized id loads ----------------
__global__ void fill_kernel(const void* __restrict__ ei) {
    int e2 = blockIdx.x * blockDim.x + threadIdx.x;
    if (2 * e2 >= N_EDGES) return;
    int s0, s1, d0, d1;
    if (g_is64) {
        longlong2 sv = ((const longlong2*)ei)[e2];
        longlong2 dv = ((const longlong2*)ei)[N_EDGES / 2 + e2];
        s0 = (int)sv.x; s1 = (int)sv.y;
        d0 = (int)dv.x; d1 = (int)dv.y;
    } else {
        int2 sv = ((const int2*)ei)[e2];
        int2 dv = ((const int2*)((const int*)ei + N_EDGES))[e2];
        s0 = sv.x; s1 = sv.y;
        d0 = dv.x; d1 = dv.y;
    }
    if ((unsigned)s0 < (unsigned)N_NODES && (unsigned)d0 < (unsigned)N_NODES) {
        int pos = atomicAdd(&g_cursor[d0], 1);
        g_csrc[pos] = s0;
    }
    if ((unsigned)s1 < (unsigned)N_NODES && (unsigned)d1 < (unsigned)N_NODES) {
        int pos = atomicAdd(&g_cursor[d1], 1);
        g_csrc[pos] = s1;
    }
}

// ---------------- FP16 MMA helpers ----------------
__device__ __forceinline__ void mma_f16(
    float* d, const uint32_t* a, const uint32_t* b)
{
    asm volatile(
        "mma.sync.aligned.m16n8k16.row.col.f32.f16.f16.f32 "
        "{%0,%1,%2,%3}, {%4,%5,%6,%7}, {%8,%9}, {%0,%1,%2,%3};"
        : "+f"(d[0]), "+f"(d[1]), "+f"(d[2]), "+f"(d[3])
        : "r"(a[0]), "r"(a[1]), "r"(a[2]), "r"(a[3]), "r"(b[0]), "r"(b[1]));
}

__device__ __forceinline__ uint32_t pack_h2(float a, float b) {
    __half2 h = __floats2half2_rn(a, b);
    return *(uint32_t*)&h;
}

// ---------------- FP16 GEMM for N=128: g_hwh = [dinv .*] (A[M,K] @ Bw^T) -----
// A: fp32 external (a16=0) or fp16 g_aggh (a16=1). Bw: [128][K] fp16 n-major.
// scaleEpi: 1 -> scale row i by g_dinv[i] in epilogue (layer 2); 0 -> raw (layer 1).
__global__ __launch_bounds__(256, 2) void hgemm128_kernel(
    const float* __restrict__ A32, int a16, int b_sel, int scaleEpi, int M, int K)
{
    const __half* A16 = g_aggh;
    const __half* Bw  = b_sel ? g_w2h : g_w1h;
    __half* C = g_hwh;

    __shared__ __align__(16) uint32_t As[128 * 20];
    __shared__ __align__(16) uint32_t Bs[128 * 20];

    int tid  = threadIdx.x;
    int lane = tid & 31;
    int warp = tid >> 5;
    int r = lane >> 2, c = lane & 3;
    int m_base = (warp >> 2) * 64;
    int n_base = (warp & 3) * 32;
    int block_row = blockIdx.x * 128;

    float acc[4][4][4];
    #pragma unroll
    for (int i = 0; i < 4; i++)
        #pragma unroll
        for (int j = 0; j < 4; j++)
            #pragma unroll
            for (int q = 0; q < 4; q++) acc[i][j][q] = 0.f;

    int a_m[4], a_kq[4];
    #pragma unroll
    for (int j = 0; j < 4; j++) {
        int u = tid + 256 * j;
        a_m[j]  = u >> 3;
        a_kq[j] = u & 7;
    }
    int c_row0 = tid >> 2;
    int c_row1 = (tid + 256) >> 2;
    int cq = tid & 3;
    int a_r0 = min(block_row + c_row0, M - 1);
    int a_r1 = min(block_row + c_row1, M - 1);

    float4 pa[4];
    uint4  pa16[2];
    uint4  pb16[2];

    if (a16) {
        pa16[0] = *(const uint4*)(A16 + (size_t)a_r0 * K + cq * 8);
        pa16[1] = *(const uint4*)(A16 + (size_t)a_r1 * K + cq * 8);
    } else {
        #pragma unroll
        for (int j = 0; j < 4; j++) {
            int gm = block_row + a_m[j];
            pa[j] = (gm < M) ? *(const float4*)&A32[(size_t)gm * K + a_kq[j] * 4]
                             : make_float4(0.f, 0.f, 0.f, 0.f);
        }
    }
    pb16[0] = *(const uint4*)(Bw + (size_t)c_row0 * K + cq * 8);
    pb16[1] = *(const uint4*)(Bw + (size_t)c_row1 * K + cq * 8);

    for (int k0 = 0; k0 < K; k0 += 32) {
        __syncthreads();
        if (a16) {
            *(uint4*)&As[c_row0 * 20 + cq * 4] = pa16[0];
            *(uint4*)&As[c_row1 * 20 + cq * 4] = pa16[1];
        } else {
            #pragma unroll
            for (int j = 0; j < 4; j++) {
                int base = a_m[j] * 20 + a_kq[j] * 2;
                As[base + 0] = pack_h2(pa[j].x, pa[j].y);
                As[base + 1] = pack_h2(pa[j].z, pa[j].w);
            }
        }
        *(uint4*)&Bs[c_row0 * 20 + cq * 4] = pb16[0];
        *(uint4*)&Bs[c_row1 * 20 + cq * 4] = pb16[1];
        __syncthreads();

        if (k0 + 32 < K) {
            int kn = k0 + 32;
            if (a16) {
                pa16[0] = *(const uint4*)(A16 + (size_t)a_r0 * K + kn + cq * 8);
                pa16[1] = *(const uint4*)(A16 + (size_t)a_r1 * K + kn + cq * 8);
            } else {
                #pragma unroll
                for (int j = 0; j < 4; j++) {
                    int gm = block_row + a_m[j];
                    pa[j] = (gm < M) ? *(const float4*)&A32[(size_t)gm * K + kn + a_kq[j] * 4]
                                     : make_float4(0.f, 0.f, 0.f, 0.f);
                }
            }
            pb16[0] = *(const uint4*)(Bw + (size_t)c_row0 * K + kn + cq * 8);
            pb16[1] = *(const uint4*)(Bw + (size_t)c_row1 * K + kn + cq * 8);
        }

        #pragma unroll
        for (int kk = 0; kk < 2; kk++) {
            int p0 = kk * 8 + c;
            uint32_t bf[4][2];
            #pragma unroll
            for (int ni = 0; ni < 4; ni++) {
                int n = n_base + ni * 8 + r;
                bf[ni][0] = Bs[n * 20 + p0];
                bf[ni][1] = Bs[n * 20 + p0 + 4];
            }
            #pragma unroll
            for (int mi = 0; mi < 4; mi++) {
                int i0 = (m_base + mi * 16 + r) * 20 + p0;
                int i1 = (m_base + mi * 16 + 8 + r) * 20 + p0;
                uint32_t af[4];
                af[0] = As[i0];     af[1] = As[i1];
                af[2] = As[i0 + 4]; af[3] = As[i1 + 4];
                #pragma unroll
                for (int ni = 0; ni < 4; ni++)
                    mma_f16(acc[mi][ni], af, bf[ni]);
            }
        }
    }

    #pragma unroll
    for (int mi = 0; mi < 4; mi++) {
        int gr0 = block_row + m_base + mi * 16 + r;
        float d0 = 1.f, d1 = 1.f;
        if (scaleEpi) {
            d0 = (gr0 < M)     ? g_dinv[gr0]     : 0.f;
            d1 = (gr0 + 8 < M) ? g_dinv[gr0 + 8] : 0.f;
        }
        #pragma unroll
        for (int ni = 0; ni < 4; ni++) {
            int col = n_base + ni * 8 + 2 * c;
            if (gr0 < M)
                *(__half2*)&C[(size_t)gr0 * 128 + col] =
                    __floats2half2_rn(acc[mi][ni][0] * d0, acc[mi][ni][1] * d0);
            if (gr0 + 8 < M)
                *(__half2*)&C[(size_t)(gr0 + 8) * 128 + col] =
                    __floats2half2_rn(acc[mi][ni][2] * d1, acc[mi][ni][3] * d1);
        }
    }
}

// ---------------- layer-3 SGEMM: g_hw40 = dinv .* (g_aggh[M,128] @ W3) -------
__global__ __launch_bounds__(256) void sgemm40_kernel(const float* __restrict__ B, int M)
{
    const __half* A = g_aggh;
    __half* C = g_hw40;
    __shared__ float As[16][128];
    __shared__ float Bs[16][40];

    int tid = threadIdx.x;
    int block_row = blockIdx.x * 128;
    int tr = tid >> 3;
    int tc = tid & 7;

    float acc[4][5] = {};

    for (int k0 = 0; k0 < HID_F; k0 += 16) {
        #pragma unroll
        for (int p = 0; p < 2; p++) {
            int i = tid + p * 256;
            int m = i >> 2;
            int kq = (i & 3) << 2;
            int gm = block_row + m;
            float2 f01 = make_float2(0.f, 0.f), f23 = make_float2(0.f, 0.f);
            if (gm < M) {
                uint2 u = *(const uint2*)&A[(size_t)gm * HID_F + k0 + kq];
                f01 = __half22float2(*(__half2*)&u.x);
                f23 = __half22float2(*(__half2*)&u.y);
            }
            As[kq + 0][m] = f01.x;
            As[kq + 1][m] = f01.y;
            As[kq + 2][m] = f23.x;
            As[kq + 3][m] = f23.y;
        }
        if (tid < 160) {
            int k = tid / 10;
            int n4 = (tid % 10) * 4;
            *(float4*)&Bs[k][n4] = *(const float4*)&B[(size_t)(k0 + k) * OUT_F + n4];
        }
        __syncthreads();

        #pragma unroll
        for (int k = 0; k < 16; k++) {
            float4 a4 = *(const float4*)&As[k][tr * 4];
            float a[4] = {a4.x, a4.y, a4.z, a4.w};
            float b[5];
            #pragma unroll
            for (int j = 0; j < 5; j++) b[j] = Bs[k][tc * 5 + j];
            #pragma unroll
            for (int i = 0; i < 4; i++)
                #pragma unroll
                for (int j = 0; j < 5; j++)
                    acc[i][j] += a[i] * b[j];
        }
        __syncthreads();
    }

    #pragma unroll
    for (int i = 0; i < 4; i++) {
        int gm = block_row + tr * 4 + i;
        if (gm >= M) continue;
        float di = g_dinv[gm];
        #pragma unroll
        for (int j = 0; j < 5; j++)
            C[(size_t)gm * OUT_F + tc * 5 + j] = __float2half_rn(acc[i][j] * di);
    }
}

// ---- aggregation 128-wide: g_aggh = relu(dinv[d].*(Σ + self) + b) -----------
// L1 = 1: h is UNSCALED -> multiply each edge row by dinv[src] (self by dinv[d]).
// L1 = 0: h is pre-scaled by dinv (layer-2 path).
template <int L1>
__global__ __launch_bounds__(256) void aggregate16_kernel(const float* __restrict__ bias)
{
    int warp = (blockIdx.x * blockDim.x + threadIdx.x) >> 5;
    int lane = threadIdx.x & 31;
    if (warp >= N_NODES) return;
    const uint2* HW = (const uint2*)g_hwh;
    int beg = g_off[warp], end = g_off[warp + 1];
    float4 acc = make_float4(0.f, 0.f, 0.f, 0.f);

    #define ACC_EDGE(sv) do {                                       \
        uint2 u_ = HW[(size_t)(sv) * 32 + lane];                    \
        float2 f01_ = __half22float2(*(__half2*)&u_.x);             \
        float2 f23_ = __half22float2(*(__half2*)&u_.y);             \
        if (L1) {                                                   \
            float ds_ = g_dinv[sv];                                 \
            acc.x += ds_ * f01_.x; acc.y += ds_ * f01_.y;           \
            acc.z += ds_ * f23_.x; acc.w += ds_ * f23_.y;           \
        } else {                                                    \
            acc.x += f01_.x; acc.y += f01_.y;                       \
            acc.z += f23_.x; acc.w += f23_.y;                       \
        }                                                           \
    } while (0)

    int j = beg;
    for (; j + 4 <= end; j += 4) {
        int s0 = g_csrc[j],     s1 = g_csrc[j + 1];
        int s2 = g_csrc[j + 2], s3 = g_csrc[j + 3];
        ACC_EDGE(s0); ACC_EDGE(s1); ACC_EDGE(s2); ACC_EDGE(s3);
    }
    for (; j < end; j++) { int sv = g_csrc[j]; ACC_EDGE(sv); }
    #undef ACC_EDGE

    float di = g_dinv[warp];
    uint2 u = HW[(size_t)warp * 32 + lane];
    float2 f01 = __half22float2(*(__half2*)&u.x);
    float2 f23 = __half22float2(*(__half2*)&u.y);
    float selfs = L1 ? di : 1.f;
    float4 b4 = ((const float4*)bias)[lane];
    float rx = fmaxf((acc.x + selfs * f01.x) * di + b4.x, 0.f);
    float ry = fmaxf((acc.y + selfs * f01.y) * di + b4.y, 0.f);
    float rz = fmaxf((acc.z + selfs * f23.x) * di + b4.z, 0.f);
    float rw = fmaxf((acc.w + selfs * f23.y) * di + b4.w, 0.f);
    __half2 h0 = __floats2half2_rn(rx, ry);
    __half2 h1 = __floats2half2_rn(rz, rw);
    ((uint2*)g_aggh)[(size_t)warp * 32 + lane] =
        make_uint2(*(uint32_t*)&h0, *(uint32_t*)&h1);
}

// ---- aggregation (40-wide) + fused log_softmax -> d_out ----------------------
__global__ __launch_bounds__(256) void aggregate40_lsm_kernel(
    const float* __restrict__ bias, float* __restrict__ out)
{
    int warp = (blockIdx.x * blockDim.x + threadIdx.x) >> 5;
    int lane = threadIdx.x & 31;
    if (warp >= N_NODES) return;
    bool active = lane < 10;
    const uint2* HW = (const uint2*)g_hw40;
    int beg = g_off[warp], end = g_off[warp + 1];
    float4 acc = make_float4(0.f, 0.f, 0.f, 0.f);

    #define ACC_E40(sv) do {                                        \
        if (active) {                                               \
            uint2 u_ = HW[(size_t)(sv) * 10 + lane];                \
            float2 f01_ = __half22float2(*(__half2*)&u_.x);         \
            float2 f23_ = __half22float2(*(__half2*)&u_.y);         \
            acc.x += f01_.x; acc.y += f01_.y;                       \
            acc.z += f23_.x; acc.w += f23_.y;                       \
        }                                                           \
    } while (0)

    int j = beg;
    for (; j + 4 <= end; j += 4) {
        int s0 = g_csrc[j],     s1 = g_csrc[j + 1];
        int s2 = g_csrc[j + 2], s3 = g_csrc[j + 3];
        ACC_E40(s0); ACC_E40(s1); ACC_E40(s2); ACC_E40(s3);
    }
    for (; j < end; j++) { int sv = g_csrc[j]; ACC_E40(sv); }
    #undef ACC_E40

    float4 v = make_float4(-3.4e38f, -3.4e38f, -3.4e38f, -3.4e38f);
    if (active) {
        float di = g_dinv[warp];
        uint2 u = HW[(size_t)warp * 10 + lane];
        float2 f01 = __half22float2(*(__half2*)&u.x);
        float2 f23 = __half22float2(*(__half2*)&u.y);
        float4 b4 = ((const float4*)bias)[lane];
        v.x = (acc.x + f01.x) * di + b4.x;
        v.y = (acc.y + f01.y) * di + b4.y;
        v.z = (acc.z + f23.x) * di + b4.z;
        v.w = (acc.w + f23.y) * di + b4.w;
    }

    float m = fmaxf(fmaxf(v.x, v.y), fmaxf(v.z, v.w));
    #pragma unroll
    for (int o = 16; o > 0; o >>= 1) m = fmaxf(m, __shfl_xor_sync(0xFFFFFFFFu, m, o));
    float s = 0.f;
    if (active)
        s = __expf(v.x - m) + __expf(v.y - m) + __expf(v.z - m) + __expf(v.w - m);
    #pragma unroll
    for (int o = 16; o > 0; o >>= 1) s += __shfl_xor_sync(0xFFFFFFFFu, s, o);
    float lse = m + __logf(s);

    if (active) {
        float4 r = make_float4(v.x - lse, v.y - lse, v.z - lse, v.w - lse);
        ((float4*)out)[(size_t)warp * 10 + lane] = r;
    }
}

// ---------------- launch ----------------
extern "C" void kernel_launch(void* const* d_in, const int* in_sizes, int n_in,
                              void* d_out, int out_size)
{
    const float* x  = (const float*)d_in[0];
    const void*  ei = d_in[1];
    const float* W1 = (const float*)d_in[2];
    const float* b1 = (const float*)d_in[3];
    const float* W2 = (const float*)d_in[4];
    const float* b2 = (const float*)d_in[5];
    const float* W3 = (const float*)d_in[6];
    const float* b3 = (const float*)d_in[7];
    float* out = (float*)d_out;

    const int TB = 256;
    int agg_grid  = (N_NODES * 32 + TB - 1) / TB;
    int gemm_grid = (N_NODES + 127) / 128;
    int pair_grid = (N_EDGES / 2 + TB - 1) / TB;

    // One-time resource creation on the FIRST call (the uncaptured correctness
    // run). The capture-time call then performs only launches/records/waits.
    struct Res {
        cudaStream_t s2;
        cudaEvent_t evFork, evJoin;
        Res() {
            cudaStreamCreateWithFlags(&s2, cudaStreamNonBlocking);
            cudaEventCreateWithFlags(&evFork, cudaEventDisableTiming);
            cudaEventCreateWithFlags(&evJoin, cudaEventDisableTiming);
        }
    };
    static Res res;

    // --- main stream: CSR chain; s2: layer-1 GEMM (independent of CSR) ---
    init_convw_kernel<<<N_BLKS + CONVW_BLKS, TB>>>((const int*)ei, W1, W2); // 1
    cudaEventRecord(res.evFork, 0);
    deg_kernel<<<pair_grid, TB>>>(ei);                                       // 2
    scan_p1_kernel<<<N_BLKS, SCAN_B>>>();                                    // 3
    cudaStreamWaitEvent(res.s2, res.evFork, 0);
    hgemm128_kernel<<<gemm_grid, 256, 0, res.s2>>>(x, 0, 0, 0, N_NODES, IN_F); // 4 (profiled)
    cudaEventRecord(res.evJoin, res.s2);
    scan_p23_kernel<<<N_BLKS, 256>>>();                                      // 5
    fill_kernel<<<pair_grid, TB>>>(ei);                                      // 6
    cudaStreamWaitEvent(0, res.evJoin, 0);

    aggregate16_kernel<1><<<agg_grid, TB>>>(b1);                             // 7
    hgemm128_kernel<<<gemm_grid, 256>>>(nullptr, 1, 1, 1, N_NODES, HID_F);   // 8
    aggregate16_kernel<0><<<agg_grid, TB>>>(b2);                             // 9
    sgemm40_kernel<<<gemm_grid, 256>>>(W3, N_NODES);                         // 10
    aggregate40_lsm_kernel<<<agg_grid, TB>>>(b3, out);                       // 11
}